// round 16
// baseline (speedup 1.0000x reference)
#include <cuda_runtime.h>

// e3nn uvu tensor product, HBM-bound streaming kernel.
//   x: (B, 1024) = 256x0e + 256x1o (u-major triplets)
//   y: (B, 4), w: (1280,), out: (B, 1024)
//
// out0[u]   = C0*w0[u]*x0[u]*y0 + C0*C1*w1[u]*dot(x1[u], y1)
// out1[u,k] = C1*w2[u]*x0[u]*y1[k] + C1*w3[u]*y0*x1[u,k] + C2*w4[u]*cross(x1[u],y1)[k]
//
// R12: scale the batched-R/W-run lever (R11 win): 4 row-groups per thread
// (ZPB=16). One read run of 20 LDG.128, one write run of 16 STG.128 per
// thread. Weights in registers.

#define NG  4           // row-groups per thread
#define ZPB (NG * 4)    // 16 batch rows per block
#define THREADS 256     // 4 row-slices x 64 u-groups

__global__ __launch_bounds__(THREADS)
void tp_uvu_kernel(const float* __restrict__ x,
                   const float* __restrict__ y,
                   const float* __restrict__ w,
                   float* __restrict__ out,
                   int B)
{
    const int tid = threadIdx.x;
    const int ug  = tid & 63;        // u-group: 4 consecutive u's
    const int zl  = tid >> 6;        // 0..3 row slice within block
    const int u   = ug << 2;

    const float C0  = 0.70710678118654752f;   // 1/sqrt(2)
    const float C1  = 0.57735026918962576f;   // 1/sqrt(3)
    const float C01 = C0 * C1;
    const float C2  = 0.40824829046386302f;   // 1/sqrt(6)

    const float4 w0 = *(const float4*)(w + 0 * 256 + u);
    const float4 w1 = *(const float4*)(w + 1 * 256 + u);
    const float4 w2 = *(const float4*)(w + 2 * 256 + u);
    const float4 w3 = *(const float4*)(w + 3 * 256 + u);
    const float4 w4 = *(const float4*)(w + 4 * 256 + u);

    const float a0[4] = {C0 * w0.x, C0 * w0.y, C0 * w0.z, C0 * w0.w};
    const float a1[4] = {C01 * w1.x, C01 * w1.y, C01 * w1.z, C01 * w1.w};
    const float a2[4] = {C1 * w2.x, C1 * w2.y, C1 * w2.z, C1 * w2.w};
    const float a3[4] = {C1 * w3.x, C1 * w3.y, C1 * w3.z, C1 * w3.w};
    const float a4[4] = {C2 * w4.x, C2 * w4.y, C2 * w4.z, C2 * w4.w};

    const int zbase = blockIdx.x * ZPB + zl;
    // Fast path requires all NG rows valid; B=131072 is divisible by 16.
    if (zbase + (NG - 1) * 4 >= B) {
        // tail: per-group guarded processing (not taken when B % 16 == 0)
        for (int g = 0; g < NG; ++g) {
            const int z = zbase + g * 4;
            if (z >= B) return;
            const float* xr   = x   + (size_t)z * 1024;
            float*       orow = out + (size_t)z * 1024;
            const float4 yv  = *(const float4*)(y + (size_t)z * 4);
            const float4 x0v = *(const float4*)(xr + u);
            const float4 xa  = *(const float4*)(xr + 256 + u * 3);
            const float4 xb  = *(const float4*)(xr + 256 + u * 3 + 4);
            const float4 xc  = *(const float4*)(xr + 256 + u * 3 + 8);
            const float y0 = yv.x, e1x = yv.y, e1y = yv.z, e1z = yv.w;
            const float vx[4]  = {xa.x, xa.w, xb.z, xc.y};
            const float vy[4]  = {xa.y, xb.x, xb.w, xc.z};
            const float vz[4]  = {xa.z, xb.y, xc.x, xc.w};
            const float x0s[4] = {x0v.x, x0v.y, x0v.z, x0v.w};
            float o0[4], ox[4], oy[4], oz[4];
            #pragma unroll
            for (int j = 0; j < 4; ++j) {
                const float dot = vx[j] * e1x + vy[j] * e1y + vz[j] * e1z;
                o0[j] = a0[j] * x0s[j] * y0 + a1[j] * dot;
                const float cx = vy[j] * e1z - vz[j] * e1y;
                const float cy = vz[j] * e1x - vx[j] * e1z;
                const float cz = vx[j] * e1y - vy[j] * e1x;
                const float s2 = a2[j] * x0s[j];
                const float s3 = a3[j] * y0;
                ox[j] = s2 * e1x + s3 * vx[j] + a4[j] * cx;
                oy[j] = s2 * e1y + s3 * vy[j] + a4[j] * cy;
                oz[j] = s2 * e1z + s3 * vz[j] + a4[j] * cz;
            }
            *(float4*)(orow + u) = make_float4(o0[0], o0[1], o0[2], o0[3]);
            *(float4*)(orow + 256 + u * 3)     = make_float4(ox[0], oy[0], oz[0], ox[1]);
            *(float4*)(orow + 256 + u * 3 + 4) = make_float4(oy[1], oz[1], ox[2], oy[2]);
            *(float4*)(orow + 256 + u * 3 + 8) = make_float4(oz[2], ox[3], oy[3], oz[3]);
        }
        return;
    }

    // ── READ RUN: all 20 LDG.128 back-to-back ──
    float4 yv[NG], x0v[NG], xa[NG], xb[NG], xc[NG];
    #pragma unroll
    for (int g = 0; g < NG; ++g) {
        const int z = zbase + g * 4;
        const float* xr = x + (size_t)z * 1024;
        yv[g]  = *(const float4*)(y + (size_t)z * 4);
        x0v[g] = *(const float4*)(xr + u);
        xa[g]  = *(const float4*)(xr + 256 + u * 3);
        xb[g]  = *(const float4*)(xr + 256 + u * 3 + 4);
        xc[g]  = *(const float4*)(xr + 256 + u * 3 + 8);
    }

    // ── COMPUTE all groups (in-place: results overwrite load regs) ──
    float4 ra[NG], rb[NG], rc[NG], rd[NG];
    #pragma unroll
    for (int g = 0; g < NG; ++g) {
        const float y0 = yv[g].x, e1x = yv[g].y, e1y = yv[g].z, e1z = yv[g].w;
        const float vx[4]  = {xa[g].x, xa[g].w, xb[g].z, xc[g].y};
        const float vy[4]  = {xa[g].y, xb[g].x, xb[g].w, xc[g].z};
        const float vz[4]  = {xa[g].z, xb[g].y, xc[g].x, xc[g].w};
        const float x0s[4] = {x0v[g].x, x0v[g].y, x0v[g].z, x0v[g].w};

        float o0[4], ox[4], oy[4], oz[4];
        #pragma unroll
        for (int j = 0; j < 4; ++j) {
            const float dot = vx[j] * e1x + vy[j] * e1y + vz[j] * e1z;
            o0[j] = a0[j] * x0s[j] * y0 + a1[j] * dot;

            const float cx = vy[j] * e1z - vz[j] * e1y;
            const float cy = vz[j] * e1x - vx[j] * e1z;
            const float cz = vx[j] * e1y - vy[j] * e1x;

            const float s2 = a2[j] * x0s[j];
            const float s3 = a3[j] * y0;

            ox[j] = s2 * e1x + s3 * vx[j] + a4[j] * cx;
            oy[j] = s2 * e1y + s3 * vy[j] + a4[j] * cy;
            oz[j] = s2 * e1z + s3 * vz[j] + a4[j] * cz;
        }

        ra[g] = make_float4(o0[0], o0[1], o0[2], o0[3]);
        rb[g] = make_float4(ox[0], oy[0], oz[0], ox[1]);
        rc[g] = make_float4(oy[1], oz[1], ox[2], oy[2]);
        rd[g] = make_float4(oz[2], ox[3], oy[3], oz[3]);
    }

    // ── WRITE RUN: all 16 STG.128 back-to-back ──
    #pragma unroll
    for (int g = 0; g < NG; ++g) {
        const int z = zbase + g * 4;
        float* orow = out + (size_t)z * 1024;
        *(float4*)(orow + u)               = ra[g];
        *(float4*)(orow + 256 + u * 3)     = rb[g];
        *(float4*)(orow + 256 + u * 3 + 4) = rc[g];
        *(float4*)(orow + 256 + u * 3 + 8) = rd[g];
    }
}

extern "C" void kernel_launch(void* const* d_in, const int* in_sizes, int n_in,
                              void* d_out, int out_size)
{
    const float* x = (const float*)d_in[0];
    const float* y = (const float*)d_in[1];
    const float* w = (const float*)d_in[2];
    float* out = (float*)d_out;

    const int B = in_sizes[0] / 1024;
    const int grid = (B + ZPB - 1) / ZPB;
    tp_uvu_kernel<<<grid, THREADS>>>(x, y, w, out, B);
}

// round 17
// speedup vs baseline: 1.1900x; 1.1900x over previous
#include <cuda_runtime.h>

// e3nn uvu tensor product, HBM-bound streaming kernel.
//   x: (B, 1024) = 256x0e + 256x1o (u-major triplets)
//   y: (B, 4), w: (1280,), out: (B, 1024)
//
// out0[u]   = C0*w0[u]*x0[u]*y0 + C0*C1*w1[u]*dot(x1[u], y1)
// out1[u,k] = C1*w2[u]*x0[u]*y1[k] + C1*w3[u]*y0*x1[u,k] + C2*w4[u]*cross(x1[u],y1)[k]
//
// R13: batched R/W runs, NG=3 (between R11's NG=2 win at 155.9us and R12's
// NG=4 register-cliff regression). __launch_bounds__(256,2) grants ptxas up
// to 128 regs so the staged read run survives register allocation.

#define NG  3           // row-groups per thread
#define ZPB (NG * 4)    // 12 batch rows per block
#define THREADS 256     // 4 row-slices x 64 u-groups

__global__ __launch_bounds__(THREADS, 2)
void tp_uvu_kernel(const float* __restrict__ x,
                   const float* __restrict__ y,
                   const float* __restrict__ w,
                   float* __restrict__ out,
                   int B)
{
    const int tid = threadIdx.x;
    const int ug  = tid & 63;        // u-group: 4 consecutive u's
    const int zl  = tid >> 6;        // 0..3 row slice within block
    const int u   = ug << 2;

    const float C0  = 0.70710678118654752f;   // 1/sqrt(2)
    const float C1  = 0.57735026918962576f;   // 1/sqrt(3)
    const float C01 = C0 * C1;
    const float C2  = 0.40824829046386302f;   // 1/sqrt(6)

    const float4 w0 = *(const float4*)(w + 0 * 256 + u);
    const float4 w1 = *(const float4*)(w + 1 * 256 + u);
    const float4 w2 = *(const float4*)(w + 2 * 256 + u);
    const float4 w3 = *(const float4*)(w + 3 * 256 + u);
    const float4 w4 = *(const float4*)(w + 4 * 256 + u);

    const float a0[4] = {C0 * w0.x, C0 * w0.y, C0 * w0.z, C0 * w0.w};
    const float a1[4] = {C01 * w1.x, C01 * w1.y, C01 * w1.z, C01 * w1.w};
    const float a2[4] = {C1 * w2.x, C1 * w2.y, C1 * w2.z, C1 * w2.w};
    const float a3[4] = {C1 * w3.x, C1 * w3.y, C1 * w3.z, C1 * w3.w};
    const float a4[4] = {C2 * w4.x, C2 * w4.y, C2 * w4.z, C2 * w4.w};

    const int zbase = blockIdx.x * ZPB + zl;

    if (zbase + (NG - 1) * 4 >= B) {
        // tail: per-group guarded (taken by the last block since B%12!=0)
        #pragma unroll 1
        for (int g = 0; g < NG; ++g) {
            const int z = zbase + g * 4;
            if (z >= B) return;
            const float* xr   = x   + (size_t)z * 1024;
            float*       orow = out + (size_t)z * 1024;
            const float4 yv  = *(const float4*)(y + (size_t)z * 4);
            const float4 x0v = *(const float4*)(xr + u);
            const float4 xa  = *(const float4*)(xr + 256 + u * 3);
            const float4 xb  = *(const float4*)(xr + 256 + u * 3 + 4);
            const float4 xc  = *(const float4*)(xr + 256 + u * 3 + 8);
            const float y0 = yv.x, e1x = yv.y, e1y = yv.z, e1z = yv.w;
            const float vx[4]  = {xa.x, xa.w, xb.z, xc.y};
            const float vy[4]  = {xa.y, xb.x, xb.w, xc.z};
            const float vz[4]  = {xa.z, xb.y, xc.x, xc.w};
            const float x0s[4] = {x0v.x, x0v.y, x0v.z, x0v.w};
            float o0[4], ox[4], oy[4], oz[4];
            #pragma unroll
            for (int j = 0; j < 4; ++j) {
                const float dot = vx[j] * e1x + vy[j] * e1y + vz[j] * e1z;
                o0[j] = a0[j] * x0s[j] * y0 + a1[j] * dot;
                const float cx = vy[j] * e1z - vz[j] * e1y;
                const float cy = vz[j] * e1x - vx[j] * e1z;
                const float cz = vx[j] * e1y - vy[j] * e1x;
                const float s2 = a2[j] * x0s[j];
                const float s3 = a3[j] * y0;
                ox[j] = s2 * e1x + s3 * vx[j] + a4[j] * cx;
                oy[j] = s2 * e1y + s3 * vy[j] + a4[j] * cy;
                oz[j] = s2 * e1z + s3 * vz[j] + a4[j] * cz;
            }
            *(float4*)(orow + u) = make_float4(o0[0], o0[1], o0[2], o0[3]);
            *(float4*)(orow + 256 + u * 3)     = make_float4(ox[0], oy[0], oz[0], ox[1]);
            *(float4*)(orow + 256 + u * 3 + 4) = make_float4(oy[1], oz[1], ox[2], oy[2]);
            *(float4*)(orow + 256 + u * 3 + 8) = make_float4(oz[2], ox[3], oy[3], oz[3]);
        }
        return;
    }

    // ── READ RUN: all 15 LDG.128 back-to-back ──
    float4 yv[NG], x0v[NG], xa[NG], xb[NG], xc[NG];
    #pragma unroll
    for (int g = 0; g < NG; ++g) {
        const int z = zbase + g * 4;
        const float* xr = x + (size_t)z * 1024;
        yv[g]  = *(const float4*)(y + (size_t)z * 4);
        x0v[g] = *(const float4*)(xr + u);
        xa[g]  = *(const float4*)(xr + 256 + u * 3);
        xb[g]  = *(const float4*)(xr + 256 + u * 3 + 4);
        xc[g]  = *(const float4*)(xr + 256 + u * 3 + 8);
    }

    // ── COMPUTE all groups ──
    float4 ra[NG], rb[NG], rc[NG], rd[NG];
    #pragma unroll
    for (int g = 0; g < NG; ++g) {
        const float y0 = yv[g].x, e1x = yv[g].y, e1y = yv[g].z, e1z = yv[g].w;
        const float vx[4]  = {xa[g].x, xa[g].w, xb[g].z, xc[g].y};
        const float vy[4]  = {xa[g].y, xb[g].x, xb[g].w, xc[g].z};
        const float vz[4]  = {xa[g].z, xb[g].y, xc[g].x, xc[g].w};
        const float x0s[4] = {x0v[g].x, x0v[g].y, x0v[g].z, x0v[g].w};

        float o0[4], ox[4], oy[4], oz[4];
        #pragma unroll
        for (int j = 0; j < 4; ++j) {
            const float dot = vx[j] * e1x + vy[j] * e1y + vz[j] * e1z;
            o0[j] = a0[j] * x0s[j] * y0 + a1[j] * dot;

            const float cx = vy[j] * e1z - vz[j] * e1y;
            const float cy = vz[j] * e1x - vx[j] * e1z;
            const float cz = vx[j] * e1y - vy[j] * e1x;

            const float s2 = a2[j] * x0s[j];
            const float s3 = a3[j] * y0;

            ox[j] = s2 * e1x + s3 * vx[j] + a4[j] * cx;
            oy[j] = s2 * e1y + s3 * vy[j] + a4[j] * cy;
            oz[j] = s2 * e1z + s3 * vz[j] + a4[j] * cz;
        }

        ra[g] = make_float4(o0[0], o0[1], o0[2], o0[3]);
        rb[g] = make_float4(ox[0], oy[0], oz[0], ox[1]);
        rc[g] = make_float4(oy[1], oz[1], ox[2], oy[2]);
        rd[g] = make_float4(oz[2], ox[3], oy[3], oz[3]);
    }

    // ── WRITE RUN: all 12 STG.128 back-to-back ──
    #pragma unroll
    for (int g = 0; g < NG; ++g) {
        const int z = zbase + g * 4;
        float* orow = out + (size_t)z * 1024;
        *(float4*)(orow + u)               = ra[g];
        *(float4*)(orow + 256 + u * 3)     = rb[g];
        *(float4*)(orow + 256 + u * 3 + 4) = rc[g];
        *(float4*)(orow + 256 + u * 3 + 8) = rd[g];
    }
}

extern "C" void kernel_launch(void* const* d_in, const int* in_sizes, int n_in,
                              void* d_out, int out_size)
{
    const float* x = (const float*)d_in[0];
    const float* y = (const float*)d_in[1];
    const float* w = (const float*)d_in[2];
    float* out = (float*)d_out;

    const int B = in_sizes[0] / 1024;
    const int grid = (B + ZPB - 1) / ZPB;
    tp_uvu_kernel<<<grid, THREADS>>>(x, y, w, out, B);
}